// round 13
// baseline (speedup 1.0000x reference)
#include <cuda_runtime.h>
#include <cuda_fp16.h>

#define Bb 32
#define Nn 512
#define Mm 512
#define KD 64
#define SPAD 1024             // padded s-extent per row (s = i'+j' in [0,1022])
#define BIGV 1e10f
#define LOG2E 1.44269504088896340736f
#define LN2   0.69314718055994530942f

#define NW 16                 // warps per CTA (dp), 32-row strips
#define BND_LEN 1056
#define NCHUNK 40
#define SMEM_DP (NW * BND_LEN * 4 + (NW - 1) * NCHUNK * 4)

// Skewed cost matrix, base-2 units: g_D[b][i'][s] = log2(e)*D[b][i'][s-i']
__device__ __half g_D[(size_t)Bb * Nn * SPAD];

__device__ __forceinline__ float ex2f(float x) {
    float r; asm("ex2.approx.f32 %0, %1;" : "=f"(r) : "f"(x)); return r;
}
__device__ __forceinline__ float lg2f(float x) {
    float r; asm("lg2.approx.f32 %0, %1;" : "=f"(r) : "f"(x)); return r;
}

struct Pack8 { __half h[8]; };

// ---------------------------------------------------------------------------
// Kernel 1: cost matrix via Gram trick (unchanged).
// ---------------------------------------------------------------------------
__global__ __launch_bounds__(256) void cost_kernel(const float* __restrict__ X,
                                                   const float* __restrict__ Y,
                                                   const int* __restrict__ Xl,
                                                   const int* __restrict__ Yl) {
    const int I0 = blockIdx.x * 64;
    const int J0 = blockIdx.y * 64;
    const int b  = blockIdx.z;
    if (I0 >= Xl[b] || J0 >= Yl[b]) return;

    __shared__ float Xs[64 * 68];
    __shared__ float Yt[64 * 68];
    __shared__ float xn[64], yn[64];

    const int tid = threadIdx.x;
    {
        int lr = tid >> 4;
        int lc = (tid & 15) * 4;
        #pragma unroll
        for (int rr = 0; rr < 64; rr += 16) {
            float4 vx = *(const float4*)&X[((size_t)(b * Nn + I0 + lr + rr)) * KD + lc];
            *(float4*)&Xs[(lr + rr) * 68 + lc] = vx;
            float4 vy = *(const float4*)&Y[((size_t)(b * Mm + J0 + lr + rr)) * KD + lc];
            Yt[(lc + 0) * 68 + lr + rr] = vy.x;
            Yt[(lc + 1) * 68 + lr + rr] = vy.y;
            Yt[(lc + 2) * 68 + lr + rr] = vy.z;
            Yt[(lc + 3) * 68 + lr + rr] = vy.w;
        }
    }
    __syncthreads();

    if (tid < 128) {
        int i = tid & 63;
        float s = 0.f;
        if (tid < 64) {
            #pragma unroll 8
            for (int k = 0; k < 64; k++) { float v = Xs[i * 68 + k]; s = fmaf(v, v, s); }
            xn[i] = s;
        } else {
            #pragma unroll 8
            for (int k = 0; k < 64; k++) { float v = Yt[k * 68 + i]; s = fmaf(v, v, s); }
            yn[i] = s;
        }
    }
    __syncthreads();

    const int ty4 = (tid >> 4) * 4;
    const int tx4 = (tid & 15) * 4;
    float acc[4][4];
    #pragma unroll
    for (int r = 0; r < 4; r++)
        #pragma unroll
        for (int c = 0; c < 4; c++) acc[r][c] = 0.f;

    #pragma unroll 4
    for (int k = 0; k < KD; k++) {
        float a0 = Xs[(ty4 + 0) * 68 + k];
        float a1 = Xs[(ty4 + 1) * 68 + k];
        float a2 = Xs[(ty4 + 2) * 68 + k];
        float a3 = Xs[(ty4 + 3) * 68 + k];
        float4 bv = *(const float4*)&Yt[k * 68 + tx4];
        acc[0][0] = fmaf(a0, bv.x, acc[0][0]); acc[0][1] = fmaf(a0, bv.y, acc[0][1]);
        acc[0][2] = fmaf(a0, bv.z, acc[0][2]); acc[0][3] = fmaf(a0, bv.w, acc[0][3]);
        acc[1][0] = fmaf(a1, bv.x, acc[1][0]); acc[1][1] = fmaf(a1, bv.y, acc[1][1]);
        acc[1][2] = fmaf(a1, bv.z, acc[1][2]); acc[1][3] = fmaf(a1, bv.w, acc[1][3]);
        acc[2][0] = fmaf(a2, bv.x, acc[2][0]); acc[2][1] = fmaf(a2, bv.y, acc[2][1]);
        acc[2][2] = fmaf(a2, bv.z, acc[2][2]); acc[2][3] = fmaf(a2, bv.w, acc[2][3]);
        acc[3][0] = fmaf(a3, bv.x, acc[3][0]); acc[3][1] = fmaf(a3, bv.y, acc[3][1]);
        acc[3][2] = fmaf(a3, bv.z, acc[3][2]); acc[3][3] = fmaf(a3, bv.w, acc[3][3]);
    }

    float y0 = yn[tx4 + 0], y1 = yn[tx4 + 1], y2 = yn[tx4 + 2], y3 = yn[tx4 + 3];
    #pragma unroll
    for (int r = 0; r < 4; r++) {
        int gi = I0 + ty4 + r;
        float xr = xn[ty4 + r];
        __half* dst = g_D + ((size_t)(b * Nn + gi)) * SPAD + (gi + J0 + tx4);
        dst[0] = __float2half(LOG2E * (xr + y0 - 2.f * acc[r][0]));
        dst[1] = __float2half(LOG2E * (xr + y1 - 2.f * acc[r][1]));
        dst[2] = __float2half(LOG2E * (xr + y2 - 2.f * acc[r][2]));
        dst[3] = __float2half(LOG2E * (xr + y3 - 2.f * acc[r][3]));
    }
}

// ---------------------------------------------------------------------------
// Kernel 2: barrier-free pipelined wavefront, 16 warps x 32-row strips,
// 1 cell per lane. Warp w owns rows [32w+1, 32w+32]; lane l -> row 32w+l+1.
// Chunk c covers diagonals [32c+2, 32c+33]. Warp w publishes its bottom row
// (32w+32) into BND[w+1][d], flags the chunk; warp w+1 spin-polls the flag.
// Warp w>0 warms up on chunk w-1 (all-dead cells) purely to stream its lane-0
// boundary registers (up1/up2) from BND before its live window starts.
// ---------------------------------------------------------------------------
__global__ __launch_bounds__(NW * 32) void dp_kernel(const int* __restrict__ Xl,
                                                     const int* __restrict__ Yl,
                                                     float* __restrict__ out) {
    extern __shared__ float smdyn[];
    float* BND = smdyn;                            // [NW][BND_LEN]
    int*   FLG = (int*)(smdyn + NW * BND_LEN);     // [NW-1][NCHUNK]

    const int b    = blockIdx.x;
    const int t    = threadIdx.x;
    const int w    = t >> 5;
    const int lane = t & 31;

    for (int idx = t; idx < BND_LEN; idx += NW * 32) BND[idx] = BIGV;   // row 0
    for (int idx = t; idx < (NW - 1) * NCHUNK; idx += NW * 32) FLG[idx] = 0;
    __syncthreads();

    const int it = Xl[b];
    const int jt = Yl[b];
    const int td = it + jt;
    const int c_end = (td - 2) >> 5;

    const int i = 32 * w + lane + 1;               // owned row
    const bool rowlive = (i <= it);
    const int dlo  = rowlive ? (i + 1) : 0x40000000;
    const unsigned rng = (unsigned)(jt - 1);       // live: (unsigned)(d-dlo) <= rng
    const int dcap = (i == it) ? td : -1;

    const bool warp_dead = (32 * w + 1 > it);
    const int c_lo = warp_dead ? (c_end + 1) : ((w > 0) ? (w - 1) : 0);
    const int c_hi = warp_dead ? c_end
                   : min((min(32 * w + 32, it) + jt - 2) >> 5, c_end);

    const bool pub = (w < NW - 1);
    float* mybnd = BND + (size_t)w * BND_LEN;
    float* nxbnd = BND + (size_t)(w + 1) * BND_LEN;

    // ---- fast phase 1: publish BIG for chunks before the live window ----
    for (int c = 0; c < c_lo && c <= c_end; ++c) {
        if (pub) {
            nxbnd[32 * c + 2 + lane] = BIGV;
            __syncwarp();
            __threadfence_block();
            if (lane == 0) *(volatile int*)&FLG[w * NCHUNK + c] = 1;
        }
    }

    // ---- live window ----
    float up1 = BIGV;                      // R(i-1, d-1)
    float up2 = (t == 0) ? 0.f : BIGV;     // R(i-1, d-2); seed R[0,0]=0
    float v1  = BIGV;                      // R(i,   d-1)
    float outv = 0.f;

    const int4* Drow = (const int4*)(g_D + ((size_t)b * Nn + (i - 1)) * SPAD);
    int q0 = min(4 * c_lo, 126);
    int4 cur = Drow[q0], nxt = Drow[q0 + 1];

    for (int c = c_lo; c <= c_hi; ++c) {
        if (w > 0) {
            volatile int* f = (volatile int*)&FLG[(w - 1) * NCHUNK + c];
            while (!*f) {}
            __threadfence_block();
        }
        const int dbase = 32 * c + 2;
        #pragma unroll
        for (int blk = 0; blk < 4; ++blk) {
            int qn = min(4 * c + blk + 2, 127);
            int4 pf = Drow[qn];
            Pack8 pk = (Pack8&)cur;
            #pragma unroll
            for (int u = 0; u < 8; ++u) {
                const int d = dbase + blk * 8 + u;
                float m  = fminf(up2, fminf(up1, v1));
                float t1 = (m == up2) ? (m - up1) : (m - up2);
                float t2 = (m == up2) ? (m - v1)
                                      : ((m == up1) ? (m - v1) : (m - up1));
                float soft = m - lg2f(1.f + ex2f(t1) + ex2f(t2));
                bool live = (unsigned)(d - dlo) <= rng;
                float nv = live ? (__half2float(pk.h[u]) + soft) : BIGV;
                if (d == dcap) outv = nv;
                if (pub && lane == 31) nxbnd[d] = nv;
                float sh = __shfl_up_sync(0xffffffffu, nv, 1);
                float bv = mybnd[d];
                up2 = up1;
                up1 = (lane == 0) ? bv : sh;
                v1  = nv;
            }
            cur = nxt; nxt = pf;
        }
        if (pub) {
            __syncwarp();
            __threadfence_block();
            if (lane == 0) *(volatile int*)&FLG[w * NCHUNK + c] = 1;
        }
    }

    // ---- fast phase 2: publish BIG for chunks after the live window ----
    for (int c = c_hi + 1; c <= c_end; ++c) {
        if (pub) {
            nxbnd[32 * c + 2 + lane] = BIGV;
            __syncwarp();
            __threadfence_block();
            if (lane == 0) *(volatile int*)&FLG[w * NCHUNK + c] = 1;
        }
    }

    if (dcap >= 0) out[b] = outv * LN2;
}

// ---------------------------------------------------------------------------
extern "C" void kernel_launch(void* const* d_in, const int* in_sizes, int n_in,
                              void* d_out, int out_size) {
    const float* X  = (const float*)d_in[0];
    const float* Y  = (const float*)d_in[1];
    const int*   Xl = (const int*)d_in[2];
    const int*   Yl = (const int*)d_in[3];
    float* out = (float*)d_out;

    static int smset = 0;
    if (!smset) {
        cudaFuncSetAttribute(dp_kernel,
                             cudaFuncAttributeMaxDynamicSharedMemorySize, SMEM_DP);
        smset = 1;
    }

    dim3 gcost(Nn / 64, Mm / 64, Bb);
    cost_kernel<<<gcost, 256>>>(X, Y, Xl, Yl);
    dp_kernel<<<Bb, NW * 32, SMEM_DP>>>(Xl, Yl, out);
}

// round 17
// speedup vs baseline: 1.0417x; 1.0417x over previous
#include <cuda_runtime.h>
#include <cuda_fp16.h>

#define Bb 32
#define Nn 512
#define Mm 512
#define KD 64
#define SPAD 1024             // padded s-extent per row (s = (i-1)+(j-1) in [0,1022])
#define BIGV 1e10f
#define LOG2E 1.44269504088896340736f
#define LN2   0.69314718055994530942f

#define NW 8                  // warps per CTA (dp), 64-row strips, 2 rows/lane
#define CHUNK 16              // diagonals per flag chunk
#define BND_LEN 1056
#define NCHUNK 66             // c_end <= (1024-2)/16 = 63

// Skewed cost matrix, base-2 units: g_D[b][i'][s] = log2(e)*D[b][i'][s-i']
__device__ __half g_D[(size_t)Bb * Nn * SPAD];

__device__ __forceinline__ float ex2f(float x) {
    float r; asm("ex2.approx.f32 %0, %1;" : "=f"(r) : "f"(x)); return r;
}
__device__ __forceinline__ float lg2f(float x) {
    float r; asm("lg2.approx.f32 %0, %1;" : "=f"(r) : "f"(x)); return r;
}

struct Pack8 { __half h[8]; };

// ---------------------------------------------------------------------------
// Kernel 1: cost matrix via Gram trick (unchanged).
// ---------------------------------------------------------------------------
__global__ __launch_bounds__(256) void cost_kernel(const float* __restrict__ X,
                                                   const float* __restrict__ Y,
                                                   const int* __restrict__ Xl,
                                                   const int* __restrict__ Yl) {
    const int I0 = blockIdx.x * 64;
    const int J0 = blockIdx.y * 64;
    const int b  = blockIdx.z;
    if (I0 >= Xl[b] || J0 >= Yl[b]) return;

    __shared__ float Xs[64 * 68];
    __shared__ float Yt[64 * 68];
    __shared__ float xn[64], yn[64];

    const int tid = threadIdx.x;
    {
        int lr = tid >> 4;
        int lc = (tid & 15) * 4;
        #pragma unroll
        for (int rr = 0; rr < 64; rr += 16) {
            float4 vx = *(const float4*)&X[((size_t)(b * Nn + I0 + lr + rr)) * KD + lc];
            *(float4*)&Xs[(lr + rr) * 68 + lc] = vx;
            float4 vy = *(const float4*)&Y[((size_t)(b * Mm + J0 + lr + rr)) * KD + lc];
            Yt[(lc + 0) * 68 + lr + rr] = vy.x;
            Yt[(lc + 1) * 68 + lr + rr] = vy.y;
            Yt[(lc + 2) * 68 + lr + rr] = vy.z;
            Yt[(lc + 3) * 68 + lr + rr] = vy.w;
        }
    }
    __syncthreads();

    if (tid < 128) {
        int i = tid & 63;
        float s = 0.f;
        if (tid < 64) {
            #pragma unroll 8
            for (int k = 0; k < 64; k++) { float v = Xs[i * 68 + k]; s = fmaf(v, v, s); }
            xn[i] = s;
        } else {
            #pragma unroll 8
            for (int k = 0; k < 64; k++) { float v = Yt[k * 68 + i]; s = fmaf(v, v, s); }
            yn[i] = s;
        }
    }
    __syncthreads();

    const int ty4 = (tid >> 4) * 4;
    const int tx4 = (tid & 15) * 4;
    float acc[4][4];
    #pragma unroll
    for (int r = 0; r < 4; r++)
        #pragma unroll
        for (int c = 0; c < 4; c++) acc[r][c] = 0.f;

    #pragma unroll 4
    for (int k = 0; k < KD; k++) {
        float a0 = Xs[(ty4 + 0) * 68 + k];
        float a1 = Xs[(ty4 + 1) * 68 + k];
        float a2 = Xs[(ty4 + 2) * 68 + k];
        float a3 = Xs[(ty4 + 3) * 68 + k];
        float4 bv = *(const float4*)&Yt[k * 68 + tx4];
        acc[0][0] = fmaf(a0, bv.x, acc[0][0]); acc[0][1] = fmaf(a0, bv.y, acc[0][1]);
        acc[0][2] = fmaf(a0, bv.z, acc[0][2]); acc[0][3] = fmaf(a0, bv.w, acc[0][3]);
        acc[1][0] = fmaf(a1, bv.x, acc[1][0]); acc[1][1] = fmaf(a1, bv.y, acc[1][1]);
        acc[1][2] = fmaf(a1, bv.z, acc[1][2]); acc[1][3] = fmaf(a1, bv.w, acc[1][3]);
        acc[2][0] = fmaf(a2, bv.x, acc[2][0]); acc[2][1] = fmaf(a2, bv.y, acc[2][1]);
        acc[2][2] = fmaf(a2, bv.z, acc[2][2]); acc[2][3] = fmaf(a2, bv.w, acc[2][3]);
        acc[3][0] = fmaf(a3, bv.x, acc[3][0]); acc[3][1] = fmaf(a3, bv.y, acc[3][1]);
        acc[3][2] = fmaf(a3, bv.z, acc[3][2]); acc[3][3] = fmaf(a3, bv.w, acc[3][3]);
    }

    float y0 = yn[tx4 + 0], y1 = yn[tx4 + 1], y2 = yn[tx4 + 2], y3 = yn[tx4 + 3];
    #pragma unroll
    for (int r = 0; r < 4; r++) {
        int gi = I0 + ty4 + r;
        float xr = xn[ty4 + r];
        __half* dst = g_D + ((size_t)(b * Nn + gi)) * SPAD + (gi + J0 + tx4);
        dst[0] = __float2half(LOG2E * (xr + y0 - 2.f * acc[r][0]));
        dst[1] = __float2half(LOG2E * (xr + y1 - 2.f * acc[r][1]));
        dst[2] = __float2half(LOG2E * (xr + y2 - 2.f * acc[r][2]));
        dst[3] = __float2half(LOG2E * (xr + y3 - 2.f * acc[r][3]));
    }
}

// ---------------------------------------------------------------------------
// Kernel 2: barrier-free pipelined wavefront, 8 warps x 64-row strips,
// 2 rows/lane (i1 = 64w+2l+1, i2 = i1+1). Both cells per step depend only on
// previous-step registers. Per step: 1 LDS (boundary, broadcast), 1 @P STS
// (lane 31 publish), 1 shfl, 2 softmins. No branches in the inner loop.
// Warp w publishes its bottom row into BND[w+1][d]; flags every CHUNK=16
// diagonals; warp w+1 spin-polls. All warps publish (dummy row for last).
// ---------------------------------------------------------------------------
__global__ __launch_bounds__(NW * 32) void dp_kernel(const int* __restrict__ Xl,
                                                     const int* __restrict__ Yl,
                                                     float* __restrict__ out) {
    __shared__ float BND[NW + 1][BND_LEN];
    __shared__ int   FLG[NW][NCHUNK];

    const int b    = blockIdx.x;
    const int t    = threadIdx.x;
    const int w    = t >> 5;
    const int lane = t & 31;

    for (int idx = t; idx < BND_LEN; idx += NW * 32) BND[0][idx] = BIGV;
    for (int idx = t; idx < NW * NCHUNK; idx += NW * 32) ((int*)FLG)[idx] = 0;
    __syncthreads();

    const int it = Xl[b];
    const int jt = Yl[b];
    const int td = it + jt;
    const int c_end = (td - 2) >> 4;

    const int i1 = 64 * w + 2 * lane + 1;
    const int i2 = i1 + 1;
    const int dlo1 = i1 + 1, dlo2 = i2 + 1;
    const unsigned rng = (unsigned)(jt - 1);      // live: (unsigned)(d-dlo) <= rng

    const bool io1 = (i1 == it), io2 = (i2 == it);
    const int  tdx = (io1 || io2) ? td : -1;

    const bool warp_dead = (64 * w + 1 > it);
    const int c_lo = warp_dead ? (c_end + 1) : ((w > 0) ? (4 * w - 1) : 0);
    const int c_hi = warp_dead ? c_end
                   : min((min(64 * w + 64, it) + jt - 2) >> 4, c_end);

    float* mybnd = BND[w];
    float* nxbnd = BND[w + 1];
    int*   myflg = FLG[w];

    // ---- fast phase 1: publish BIG for chunks before the live window ----
    for (int c = 0; c < c_lo && c <= c_end; ++c) {
        if (lane < CHUNK) nxbnd[CHUNK * c + 2 + lane] = BIGV;
        __syncwarp();
        __threadfence_block();
        if (lane == 0) *(volatile int*)&myflg[c] = 1;
    }

    // ---- live window (includes one warm-up chunk to seed up1/up2) ----
    float up1 = BIGV;                      // R(i1-1, d-1)
    float up2 = (t == 0) ? 0.f : BIGV;     // R(i1-1, d-2); seed R[0,0]=0
    float v1a = BIGV;                      // R(i1, d-1)
    float v1b = BIGV;                      // R(i2, d-1)
    float v2a = BIGV;                      // R(i1, d-2)
    float outv = 0.f;

    const int4* DrA = (const int4*)(g_D + ((size_t)b * Nn + (i1 - 1)) * SPAD);
    const int4* DrB = (const int4*)(g_D + ((size_t)b * Nn + (i2 - 1)) * SPAD);
    int q0 = min(2 * c_lo, 125);
    int4 curA = DrA[q0], nxtA = DrA[q0 + 1];
    int4 curB = DrB[q0], nxtB = DrB[q0 + 1];

    for (int c = c_lo; c <= c_hi; ++c) {
        if (w > 0) {
            volatile int* f = (volatile int*)&FLG[w - 1][c];
            while (!*f) {}
            __threadfence_block();
        }
        const int dbase = CHUNK * c + 2;
        #pragma unroll
        for (int blk = 0; blk < 2; ++blk) {
            int qn = min(2 * c + blk + 2, 127);
            int4 pfA = DrA[qn], pfB = DrB[qn];
            // hoist half->float conversions off the dependency chain
            float fA[8], fB[8];
            {
                Pack8 pa = (Pack8&)curA, pb = (Pack8&)curB;
                #pragma unroll
                for (int u = 0; u < 8; ++u) {
                    fA[u] = __half2float(pa.h[u]);
                    fB[u] = __half2float(pb.h[u]);
                }
            }
            #pragma unroll
            for (int u = 0; u < 8; ++u) {
                const int d = dbase + 8 * blk + u;
                // cell i1: a=up2, b=up1, c=v1a
                float m1 = fminf(up2, fminf(up1, v1a));
                float x1 = (m1 == up2) ? (m1 - up1) : (m1 - up2);
                float y1 = (m1 == up2) ? (m1 - v1a)
                                       : ((m1 == up1) ? (m1 - v1a) : (m1 - up1));
                float s1 = m1 - lg2f(1.f + ex2f(x1) + ex2f(y1));
                float nv1 = ((unsigned)(d - dlo1) <= rng) ? (fA[u] + s1) : BIGV;
                // cell i2: a=v2a, b=v1a, c=v1b
                float m2 = fminf(v2a, fminf(v1a, v1b));
                float x2 = (m2 == v2a) ? (m2 - v1a) : (m2 - v2a);
                float y2 = (m2 == v2a) ? (m2 - v1b)
                                       : ((m2 == v1a) ? (m2 - v1b) : (m2 - v1a));
                float s2 = m2 - lg2f(1.f + ex2f(x2) + ex2f(y2));
                float nv2 = ((unsigned)(d - dlo2) <= rng) ? (fB[u] + s2) : BIGV;
                // output capture (pure selects)
                outv = (d == tdx) ? (io1 ? nv1 : nv2) : outv;
                // publish bottom row (predicated store, no branch)
                if (lane == 31) nxbnd[d] = nv2;
                // neighbor exchange
                float sh = __shfl_up_sync(0xffffffffu, nv2, 1);
                float bv = mybnd[d];
                up2 = up1;
                up1 = (lane == 0) ? bv : sh;
                v2a = v1a; v1a = nv1; v1b = nv2;
            }
            curA = nxtA; nxtA = pfA;
            curB = nxtB; nxtB = pfB;
        }
        __syncwarp();
        __threadfence_block();
        if (lane == 0) *(volatile int*)&myflg[c] = 1;
    }

    // ---- fast phase 2: publish BIG for chunks after the live window ----
    for (int c = c_hi + 1; c <= c_end; ++c) {
        if (lane < CHUNK) nxbnd[CHUNK * c + 2 + lane] = BIGV;
        __syncwarp();
        __threadfence_block();
        if (lane == 0) *(volatile int*)&myflg[c] = 1;
    }

    if (tdx >= 0) out[b] = outv * LN2;
}

// ---------------------------------------------------------------------------
extern "C" void kernel_launch(void* const* d_in, const int* in_sizes, int n_in,
                              void* d_out, int out_size) {
    const float* X  = (const float*)d_in[0];
    const float* Y  = (const float*)d_in[1];
    const int*   Xl = (const int*)d_in[2];
    const int*   Yl = (const int*)d_in[3];
    float* out = (float*)d_out;

    dim3 gcost(Nn / 64, Mm / 64, Bb);
    cost_kernel<<<gcost, 256>>>(X, Y, Xl, Yl);
    dp_kernel<<<Bb, NW * 32>>>(Xl, Yl, out);
}